// round 1
// baseline (speedup 1.0000x reference)
#include <cuda_runtime.h>
#include <cuda_bf16.h>

// NBVLoss: weighted BCE full reduction.
//   loss = 1.6 * sum_{t==1} bce + 0.4 * sum_{t==0} bce
//   bce  = -(t*max(log p, -100) + (1-t)*max(log(1-p), -100))
// Two-pass deterministic reduction: per-block double partials -> fixed tree.

constexpr int BLOCKS  = 1184;   // 148 SMs * 8 CTAs
constexpr int THREADS = 256;
constexpr float LOG_CLAMP = -100.0f;

__device__ double g_partial[BLOCKS];

__device__ __forceinline__ float bce_w(float p, float t) {
    // __logf(0) = -inf -> clamped to -100, matching jnp.clip(log(p), -100)
    float lp = fmaxf(__logf(p),        LOG_CLAMP);
    float lq = fmaxf(__logf(1.0f - p), LOG_CLAMP);
    // t is exactly 0.0f or 1.0f
    return -(1.6f * t * lp + 0.4f * (1.0f - t) * lq);
}

__global__ void __launch_bounds__(THREADS)
bce_partial_kernel(const float4* __restrict__ pred,
                   const float4* __restrict__ targ,
                   int n4, int n_tail_base, int n_total)
{
    float local = 0.0f;

    int idx = blockIdx.x * THREADS + threadIdx.x;
    const int stride = BLOCKS * THREADS;
    for (; idx < n4; idx += stride) {
        float4 pv = pred[idx];
        float4 tv = targ[idx];
        local += bce_w(pv.x, tv.x);
        local += bce_w(pv.y, tv.y);
        local += bce_w(pv.z, tv.z);
        local += bce_w(pv.w, tv.w);
    }

    // Scalar tail (n not divisible by 4) — handled by one thread, deterministic.
    if (blockIdx.x == 0 && threadIdx.x == 0) {
        const float* ps = (const float*)pred;
        const float* ts = (const float*)targ;
        for (int i = n_tail_base; i < n_total; i++)
            local += bce_w(ps[i], ts[i]);
    }

    // Warp reduce (float), then cross-warp in double (fixed order per block).
    #pragma unroll
    for (int off = 16; off > 0; off >>= 1)
        local += __shfl_down_sync(0xFFFFFFFFu, local, off);

    __shared__ double s_warp[THREADS / 32];
    int wid = threadIdx.x >> 5;
    int lid = threadIdx.x & 31;
    if (lid == 0) s_warp[wid] = (double)local;
    __syncthreads();

    if (threadIdx.x == 0) {
        double acc = 0.0;
        #pragma unroll
        for (int w = 0; w < THREADS / 32; w++) acc += s_warp[w];
        g_partial[blockIdx.x] = acc;
    }
}

__global__ void __launch_bounds__(256)
bce_finalize_kernel(float* __restrict__ out)
{
    __shared__ double s[256];
    double v = 0.0;
    for (int i = threadIdx.x; i < BLOCKS; i += 256)
        v += g_partial[i];
    s[threadIdx.x] = v;
    __syncthreads();
    #pragma unroll
    for (int off = 128; off > 0; off >>= 1) {
        if (threadIdx.x < off) s[threadIdx.x] += s[threadIdx.x + off];
        __syncthreads();
    }
    if (threadIdx.x == 0) out[0] = (float)s[0];
}

extern "C" void kernel_launch(void* const* d_in, const int* in_sizes, int n_in,
                              void* d_out, int out_size)
{
    const float4* pred = (const float4*)d_in[0];
    const float4* targ = (const float4*)d_in[1];
    float* out = (float*)d_out;

    int n  = in_sizes[0];        // 16384*4096 = 67108864
    int n4 = n >> 2;
    int tail_base = n4 << 2;

    bce_partial_kernel<<<BLOCKS, THREADS>>>(pred, targ, n4, tail_base, n);
    bce_finalize_kernel<<<1, 256>>>(out);
}